// round 10
// baseline (speedup 1.0000x reference)
#include <cuda_runtime.h>

#define THREADS 896   // 28 warps; threads 0..783 = 196 patches x 4 sub-threads
#define NWARPS 28

// Per-thread state: 4 complex amplitudes indexed m = (b0<<1)|b1 (qubits 0,1).
// Qubit 2 bit = lane bit1 (sub&2), qubit 3 bit = lane bit0 (sub&1).
// All shfl stay inside an aligned quad of lanes.

// SU(2) gate [[a+ib, c+id],[-c+id, a-ib]] on a LOCAL qubit (mask in {2,1}).
__device__ __forceinline__ void su2_local(float* re, float* im, int mask,
                                          float a, float b, float c, float d) {
#pragma unroll
    for (int i = 0; i < 4; i++) {
        if (i & mask) continue;
        int j = i | mask;
        float r0 = re[i], i0 = im[i], r1 = re[j], i1 = im[j];
        re[i] =  a * r0 - b * i0 + c * r1 - d * i1;
        im[i] =  a * i0 + b * r0 + c * i1 + d * r1;
        re[j] = -c * r0 - d * i0 + a * r1 + b * i1;
        im[j] = -c * i0 + d * r0 + a * i1 - b * r1;
    }
}

// SU(2) on a lane-split qubit. lanemask = shfl xor distance (2 for q2, 1 for q3),
// row = this thread's bit for that qubit.
__device__ __forceinline__ void su2_split(float* re, float* im, int lanemask, int row,
                                          float a, float b, float c, float d) {
    const float e = row ? -b : b;
    const float f = row ? -c : c;
#pragma unroll
    for (int m = 0; m < 4; m++) {
        float pr = __shfl_xor_sync(0xffffffffu, re[m], lanemask);
        float pi = __shfl_xor_sync(0xffffffffu, im[m], lanemask);
        float r = re[m], i = im[m];
        re[m] = a * r - e * i + f * pr - d * pi;
        im[m] = a * i + e * r + f * pi + d * pr;
    }
}

__global__ __launch_bounds__(THREADS, 1)
void qnet_kernel(const float* __restrict__ x,       // [B,1,28,28]
                 const float* __restrict__ weight,  // [60]
                 const float* __restrict__ fc1_w,   // [64,784]
                 const float* __restrict__ fc1_b,   // [64]
                 const float* __restrict__ fc2_w,   // [10,64]
                 const float* __restrict__ fc2_b,   // [10]
                 float* __restrict__ out)           // [B,10]
{
    __shared__ float  feat[784];    // [patch*4 + q]
    __shared__ float  hidden[64];
    __shared__ float4 g[20];        // fused Ry*Rz*Ry per (layer,qubit): (a,b,c,d)

    const int b   = blockIdx.x;
    const int tid = threadIdx.x;

    // ---- Precompute fused SU(2) gates: U = Ry(p2)*Rz(p1)*Ry(p0)
    if (tid < 20) {
        const int L = tid >> 2, q = tid & 3;
        const float* p = weight + 12 * L;
        float ca, sa, cb, sb, cc, sc;
        sincosf(0.5f * p[q],     &sa, &ca);
        sincosf(0.5f * p[4 + q], &sb, &cb);
        sincosf(0.5f * p[8 + q], &sc, &cc);
        float t0 = cc * ca - sc * sa;
        float t1 = cc * ca + sc * sa;
        float t2 = cc * sa + sc * ca;
        float t3 = cc * sa - sc * ca;
        g[tid] = make_float4(cb * t0, -sb * t1, -cb * t2, sb * t3);
    }
    __syncthreads();

    // ---- Circuit: 4 threads per patch (quad). Dummy quads (tid >= 784)
    // run a clamped patch and skip the feat write; warps stay converged.
    {
        const int p_raw = tid >> 2;
        const bool valid = p_raw < 196;
        const int p   = valid ? p_raw : 195;
        const int sub = tid & 3;                 // (q2 bit << 1) | q3 bit
        const int r2  = (sub >> 1) & 1;          // qubit-2 row
        const int r3  = sub & 1;                 // qubit-3 row

        const int pi_ = p / 14, pj = p % 14;
        const float* xb = x + b * 784 + (2 * pi_) * 28 + 2 * pj;
        const float2 xr0 = *reinterpret_cast<const float2*>(xb);
        const float2 xr1 = *reinterpret_cast<const float2*>(xb + 28);
        const float ang[4] = { xr0.x, xr0.y, xr1.x, xr1.y };

        // Layer 0 fused with Rx encoding on |0000>: per qubit q,
        // V_q = G0_q * Rx(2*pi*x_q); first-column entries:
        //   row0 = (a*cx + d*sx) + i(b*cx - c*sx)
        //   row1 = (-(c*cx + b*sx)) + i(d*cx - a*sx)
        const float PI = 3.14159265358979323846f;
        float r0c[2], i0c[2], r1c[2], i1c[2];   // qubits 0,1 full columns
        float v2r, v2i, v3r, v3i;               // qubits 2,3 own-row entries
#pragma unroll
        for (int q = 0; q < 4; q++) {
            float sx, cx;
            sincosf(PI * ang[q], &sx, &cx);
            float4 G = g[q];
            float a0r =  G.x * cx + G.w * sx;
            float a0i =  G.y * cx - G.z * sx;
            float a1r = -(G.z * cx + G.y * sx);
            float a1i =  G.w * cx - G.x * sx;
            if (q < 2) {
                r0c[q] = a0r; i0c[q] = a0i;
                r1c[q] = a1r; i1c[q] = a1i;
            } else if (q == 2) {
                v2r = r2 ? a1r : a0r;
                v2i = r2 ? a1i : a0i;
            } else {
                v3r = r3 ? a1r : a0r;
                v3i = r3 ? a1i : a0i;
            }
        }

        // State = (q0 col ⊗ q1 col) scaled by own (q2 row * q3 row) component.
        float re[4], im[4];
        {
            float sr = v2r * v3r - v2i * v3i;
            float si = v2r * v3i + v2i * v3r;
#pragma unroll
            for (int b0 = 0; b0 < 2; b0++) {
                float ar = b0 ? r1c[0] : r0c[0], ai = b0 ? i1c[0] : i0c[0];
#pragma unroll
                for (int b1 = 0; b1 < 2; b1++) {
                    float br = b1 ? r1c[1] : r0c[1], bi = b1 ? i1c[1] : i0c[1];
                    float tr = ar * br - ai * bi;
                    float ti = ar * bi + ai * br;
                    re[b0 * 2 + b1] = tr * sr - ti * si;
                    im[b0 * 2 + b1] = tr * si + ti * sr;
                }
            }
        }

        // ---- Layers 1..4: CNOT ring, then fused gates
#pragma unroll
        for (int layer = 1; layer < 5; layer++) {
            // CNOT(0,1): control b0 (local bit1), target b1 (local bit0): swap (2,3)
            { float t;
              t = re[2]; re[2] = re[3]; re[3] = t;
              t = im[2]; im[2] = im[3]; im[3] = t; }
            // CNOT(1,2): control b1 (local bit0), target q2 (lane bit1):
            // amps with b1=1 exchange with lane^2
            re[1] = __shfl_xor_sync(0xffffffffu, re[1], 2);
            im[1] = __shfl_xor_sync(0xffffffffu, im[1], 2);
            re[3] = __shfl_xor_sync(0xffffffffu, re[3], 2);
            im[3] = __shfl_xor_sync(0xffffffffu, im[3], 2);
            // CNOT(2,3): control q2 (lane bit1), target q3 (lane bit0):
            // lanes with q2=1 exchange entire state with lane^1
#pragma unroll
            for (int m = 0; m < 4; m++) {
                float pr = __shfl_xor_sync(0xffffffffu, re[m], 1);
                float pim = __shfl_xor_sync(0xffffffffu, im[m], 1);
                re[m] = r2 ? pr  : re[m];
                im[m] = r2 ? pim : im[m];
            }
            // CNOT(3,0): control q3 (lane bit0), target b0 (local bit1):
            // lanes with q3=1 swap m <-> m^2
            {
                float n0r = r3 ? re[2] : re[0], n2r = r3 ? re[0] : re[2];
                float n1r = r3 ? re[3] : re[1], n3r = r3 ? re[1] : re[3];
                float n0i = r3 ? im[2] : im[0], n2i = r3 ? im[0] : im[2];
                float n1i = r3 ? im[3] : im[1], n3i = r3 ? im[1] : im[3];
                re[0] = n0r; re[1] = n1r; re[2] = n2r; re[3] = n3r;
                im[0] = n0i; im[1] = n1i; im[2] = n2i; im[3] = n3i;
            }
            // fused gates
            {
                float4 G;
                G = g[layer * 4 + 0]; su2_local(re, im, 2, G.x, G.y, G.z, G.w);
                G = g[layer * 4 + 1]; su2_local(re, im, 1, G.x, G.y, G.z, G.w);
                G = g[layer * 4 + 2]; su2_split(re, im, 2, r2, G.x, G.y, G.z, G.w);
                G = g[layer * 4 + 3]; su2_split(re, im, 1, r3, G.x, G.y, G.z, G.w);
            }
        }

        // ---- <Z_q> partials, reduce across the quad
        float e0 = 0.f, e1 = 0.f, e2 = 0.f, e3 = 0.f;
#pragma unroll
        for (int m = 0; m < 4; m++) {
            float pr = re[m] * re[m] + im[m] * im[m];
            e0 += (m & 2) ? -pr : pr;
            e1 += (m & 1) ? -pr : pr;
            e2 += r2 ? -pr : pr;
            e3 += r3 ? -pr : pr;
        }
#pragma unroll
        for (int off = 1; off <= 2; off <<= 1) {
            e0 += __shfl_xor_sync(0xffffffffu, e0, off);
            e1 += __shfl_xor_sync(0xffffffffu, e1, off);
            e2 += __shfl_xor_sync(0xffffffffu, e2, off);
            e3 += __shfl_xor_sync(0xffffffffu, e3, off);
        }

        if (valid && sub == 0) {
            feat[p * 4 + 0] = e0;
            feat[p * 4 + 1] = e1;
            feat[p * 4 + 2] = e2;
            feat[p * 4 + 3] = e3;
        }
    }
    __syncthreads();

    // ---- FC1: hidden[h] = relu(feat . fc1_w[h,:] + fc1_b[h]), one h per warp
    {
        const int warp = tid >> 5;
        const int lane = tid & 31;
        const float4* W4 = reinterpret_cast<const float4*>(fc1_w);
        const float4* F4 = reinterpret_cast<const float4*>(feat);
        for (int h = warp; h < 64; h += NWARPS) {
            float acc = 0.f;
            for (int kk = lane; kk < 196; kk += 32) {
                float4 w = W4[h * 196 + kk];
                float4 f = F4[kk];
                acc += w.x * f.x + w.y * f.y + w.z * f.z + w.w * f.w;
            }
#pragma unroll
            for (int off = 16; off; off >>= 1)
                acc += __shfl_down_sync(0xffffffffu, acc, off);
            if (lane == 0)
                hidden[h] = fmaxf(acc + fc1_b[h], 0.f);
        }
    }
    __syncthreads();

    // ---- FC2
    if (tid < 10) {
        float acc = fc2_b[tid];
#pragma unroll 8
        for (int h = 0; h < 64; h++)
            acc += hidden[h] * fc2_w[tid * 64 + h];
        out[b * 10 + tid] = acc;
    }
}

extern "C" void kernel_launch(void* const* d_in, const int* in_sizes, int n_in,
                              void* d_out, int out_size) {
    const float* x     = (const float*)d_in[0];
    const float* w     = (const float*)d_in[1];
    const float* fc1_w = (const float*)d_in[2];
    const float* fc1_b = (const float*)d_in[3];
    const float* fc2_w = (const float*)d_in[4];
    const float* fc2_b = (const float*)d_in[5];
    float* out = (float*)d_out;

    const int B = in_sizes[0] / 784;  // 128
    qnet_kernel<<<B, THREADS>>>(x, w, fc1_w, fc1_b, fc2_w, fc2_b, out);
}

// round 11
// speedup vs baseline: 1.2017x; 1.2017x over previous
#include <cuda_runtime.h>

#define THREADS 448   // 14 warps; threads 0..391 = 196 patches x 2 sub-threads
#define NWARPS 14

// 2-way split: per-thread 8 complex amps, m = (b0<<2)|(b1<<1)|b2; qubit-3 bit = sub
// (tid & 1), partner = tid^1 (same warp). Entire CNOT ring folded into gate
// coefficient variants; the only cross-thread traffic is the q3 gate's shfl.

// Plain SU(2) [[a+ib, c+id],[-c+id, a-ib]] on local qubit, with optional
// row-swap (folded post-CNOT) on pairs where (i & ctrl). All compile-time.
__device__ __forceinline__ void su2_local_rs(float* re, float* im, int mask, int ctrl,
                                             bool rs, float a, float b, float c, float d) {
#pragma unroll
    for (int i = 0; i < 8; i++) {
        if (i & mask) continue;
        int j = i | mask;
        float r0 = re[i], i0 = im[i], r1 = re[j], i1 = im[j];
        float n0r =  a * r0 - b * i0 + c * r1 - d * i1;
        float n0i =  a * i0 + b * r0 + c * i1 + d * r1;
        float n1r = -c * r0 - d * i0 + a * r1 + b * i1;
        float n1i = -c * i0 + d * r0 + a * i1 - b * r1;
        if (rs && (i & ctrl)) { re[i] = n1r; im[i] = n1i; re[j] = n0r; im[j] = n0i; }
        else                  { re[i] = n0r; im[i] = n0i; re[j] = n1r; im[j] = n1i; }
    }
}

__global__ __launch_bounds__(THREADS, 1)
void qnet_kernel(const float* __restrict__ x,       // [B,1,28,28]
                 const float* __restrict__ weight,  // [60]
                 const float* __restrict__ fc1_w,   // [64,784]
                 const float* __restrict__ fc1_b,   // [64]
                 const float* __restrict__ fc2_w,   // [10,64]
                 const float* __restrict__ fc2_b,   // [10]
                 float* __restrict__ out)           // [B,10]
{
    __shared__ float  feat[784];
    __shared__ float  hidden[64];
    __shared__ float4 g[20];        // fused Ry*Rz*Ry per (layer,qubit): (a,b,c,d)

    const int b   = blockIdx.x;
    const int tid = threadIdx.x;

    // ---- Precompute fused SU(2) gates: U = Ry(p2)*Rz(p1)*Ry(p0)
    if (tid < 20) {
        const int L = tid >> 2, q = tid & 3;
        const float* p = weight + 12 * L;
        float ca, sa, cb, sb, cc, sc;
        sincosf(0.5f * p[q],     &sa, &ca);
        sincosf(0.5f * p[4 + q], &sb, &cb);
        sincosf(0.5f * p[8 + q], &sc, &cc);
        float t0 = cc * ca - sc * sa;
        float t1 = cc * ca + sc * sa;
        float t2 = cc * sa + sc * ca;
        float t3 = cc * sa - sc * ca;
        g[tid] = make_float4(cb * t0, -sb * t1, -cb * t2, sb * t3);
    }
    __syncthreads();

    // ---- Circuit: 2 threads per patch; dummy threads (tid >= 392) run a
    // clamped patch and skip the feat write; warps stay converged.
    {
        const int p_raw = tid >> 1;
        const bool valid = p_raw < 196;
        const int p   = valid ? p_raw : 195;
        const int sub = tid & 1;                 // qubit-3 bit

        const int pi_ = p / 14, pj = p % 14;
        const float* xb = x + b * 784 + (2 * pi_) * 28 + 2 * pj;
        const float2 xr0 = *reinterpret_cast<const float2*>(xb);
        const float2 xr1 = *reinterpret_cast<const float2*>(xb + 28);
        const float ang[4] = { xr0.x, xr0.y, xr1.x, xr1.y };

        // Layer 0 fused with Rx encoding on |0000>: V_q = G0_q * Rx(2*pi*x_q),
        // keep BOTH first-column rows per qubit:
        //   row0 = (a*cx + d*sx) + i(b*cx - c*sx)
        //   row1 = (-(c*cx + b*sx)) + i(d*cx - a*sx)
        const float PI = 3.14159265358979323846f;
        float R0[4], I0[4], R1[4], I1[4];
#pragma unroll
        for (int q = 0; q < 4; q++) {
            float sx, cx;
            __sincosf(PI * ang[q], &sx, &cx);
            float4 G = g[q];
            R0[q] =  G.x * cx + G.w * sx;
            I0[q] =  G.y * cx - G.z * sx;
            R1[q] = -(G.z * cx + G.y * sx);
            I1[q] =  G.w * cx - G.x * sx;
        }

        // Ring-0's X01,X12,X23 folded into the product via twisted indexing:
        //   state[m] = A(b0) * B(b0^b1) * C(b1^b2) * D(b2^sub)
        float re[8], im[8];
        {
            // D selected by b2^sub (sub runtime, b2 compile-time)
            float Dr[2], Di[2];
            Dr[0] = sub ? R1[3] : R0[3];  Di[0] = sub ? I1[3] : I0[3];
            Dr[1] = sub ? R0[3] : R1[3];  Di[1] = sub ? I0[3] : I1[3];
#pragma unroll
            for (int b0 = 0; b0 < 2; b0++) {
                float ar = b0 ? R1[0] : R0[0], ai = b0 ? I1[0] : I0[0];
#pragma unroll
                for (int b1 = 0; b1 < 2; b1++) {
                    int ib = b0 ^ b1;
                    float br = ib ? R1[1] : R0[1], bi = ib ? I1[1] : I0[1];
                    float abr = ar * br - ai * bi;
                    float abi = ar * bi + ai * br;
#pragma unroll
                    for (int b2 = 0; b2 < 2; b2++) {
                        int ic = b1 ^ b2;
                        float cr = ic ? R1[2] : R0[2], ci = ic ? I1[2] : I0[2];
                        float tr = abr * cr - abi * ci;
                        float ti = abr * ci + abi * cr;
                        int m = b0 * 4 + b1 * 2 + b2;
                        re[m] = tr * Dr[b2] - ti * Di[b2];
                        im[m] = tr * Di[b2] + ti * Dr[b2];
                    }
                }
            }
        }

        // ---- Blocks 1..4. Each block: G0' (prev ring's X30 pre-folded:
        // column-swap for sub=1), then G1/G2 (own ring's X01/X12 post-folded:
        // row-swap on controlled half), then split-q3 gate (own ring's X23
        // post-folded: opposite-row coeffs for odd m). Block 4 has no own ring.
#pragma unroll
        for (int layer = 1; layer < 5; layer++) {
            const bool rs = (layer < 4);   // own-ring folds exist for blocks 1..3

            // G0' on q0 (mask 4): generic 8-coeff form,
            // normal: (p,q,r,s | t,u,v,w) = (a,b,c,d | -c,d,a,-b)
            // col-swapped (sub=1): (c,d,a,b | a,-b,-c,d)
            {
                float4 G = g[layer * 4 + 0];
                float a = G.x, bb = G.y, c = G.z, d = G.w;
                float p_ = sub ? c  : a;
                float q_ = sub ? d  : bb;
                float r_ = sub ? a  : c;
                float s_ = sub ? bb : d;
                float t_ = sub ? a  : -c;
                float u_ = sub ? -bb : d;
                float v_ = sub ? -c : a;
                float w_ = sub ? d  : -bb;
#pragma unroll
                for (int i = 0; i < 4; i++) {
                    int j = i | 4;
                    float r0 = re[i], i0 = im[i], r1 = re[j], i1 = im[j];
                    re[i] = p_ * r0 - q_ * i0 + r_ * r1 - s_ * i1;
                    im[i] = p_ * i0 + q_ * r0 + r_ * i1 + s_ * r1;
                    re[j] = t_ * r0 - u_ * i0 + v_ * r1 - w_ * i1;
                    im[j] = t_ * i0 + u_ * r0 + v_ * i1 + w_ * r1;
                }
            }
            // G1' on q1 (mask 2), row-swap where b0=1 (i & 4)
            {
                float4 G = g[layer * 4 + 1];
                su2_local_rs(re, im, 2, 4, rs, G.x, G.y, G.z, G.w);
            }
            // G2' on q2 (mask 1), row-swap where b1=1 (i & 2)
            {
                float4 G = g[layer * 4 + 2];
                su2_local_rs(re, im, 1, 2, rs, G.x, G.y, G.z, G.w);
            }
            // G3' on split q3; X23 fold: odd m (b2=1) uses opposite-row coeffs.
            // even (P,Q,R,S): sub ? (a,-b,-c,d) : (a,b,c,d)
            // odd           : sub ? (c,d,a,b)   : (-c,d,a,-b)   [only if rs]
            {
                float4 G = g[layer * 4 + 3];
                float a = G.x, bb = G.y, c = G.z, d = G.w;
                float Pe = a;
                float Qe = sub ? -bb : bb;
                float Re_ = sub ? -c : c;
                float Se = d;
                float Po, Qo, Ro, So;
                if (rs) {
                    Po = sub ? c : -c;
                    Qo = d;
                    Ro = a;
                    So = sub ? bb : -bb;
                } else {
                    Po = Pe; Qo = Qe; Ro = Re_; So = Se;
                }
#pragma unroll
                for (int m = 0; m < 8; m++) {
                    float pr = __shfl_xor_sync(0xffffffffu, re[m], 1);
                    float pi = __shfl_xor_sync(0xffffffffu, im[m], 1);
                    float P = (m & 1) ? Po : Pe;
                    float Q = (m & 1) ? Qo : Qe;
                    float R = (m & 1) ? Ro : Re_;
                    float S = (m & 1) ? So : Se;
                    float r = re[m], i = im[m];
                    re[m] = P * r - Q * i + R * pr - S * pi;
                    im[m] = P * i + Q * r + R * pi + S * pr;
                }
            }
        }

        // ---- <Z_q> partials, combine with partner
        float e0 = 0.f, e1 = 0.f, e2 = 0.f, e3 = 0.f;
#pragma unroll
        for (int m = 0; m < 8; m++) {
            float pr = re[m] * re[m] + im[m] * im[m];
            e0 += (m & 4) ? -pr : pr;
            e1 += (m & 2) ? -pr : pr;
            e2 += (m & 1) ? -pr : pr;
            e3 += sub ? -pr : pr;
        }
        e0 += __shfl_xor_sync(0xffffffffu, e0, 1);
        e1 += __shfl_xor_sync(0xffffffffu, e1, 1);
        e2 += __shfl_xor_sync(0xffffffffu, e2, 1);
        e3 += __shfl_xor_sync(0xffffffffu, e3, 1);

        if (valid && sub == 0) {
            feat[p * 4 + 0] = e0;
            feat[p * 4 + 1] = e1;
            feat[p * 4 + 2] = e2;
            feat[p * 4 + 3] = e3;
        }
    }
    __syncthreads();

    // ---- FC1: hidden[h] = relu(feat . fc1_w[h,:] + fc1_b[h]), one h per warp
    {
        const int warp = tid >> 5;
        const int lane = tid & 31;
        const float4* W4 = reinterpret_cast<const float4*>(fc1_w);
        const float4* F4 = reinterpret_cast<const float4*>(feat);
        for (int h = warp; h < 64; h += NWARPS) {
            float acc = 0.f;
            for (int kk = lane; kk < 196; kk += 32) {
                float4 w = W4[h * 196 + kk];
                float4 f = F4[kk];
                acc += w.x * f.x + w.y * f.y + w.z * f.z + w.w * f.w;
            }
#pragma unroll
            for (int off = 16; off; off >>= 1)
                acc += __shfl_down_sync(0xffffffffu, acc, off);
            if (lane == 0)
                hidden[h] = fmaxf(acc + fc1_b[h], 0.f);
        }
    }
    __syncthreads();

    // ---- FC2
    if (tid < 10) {
        float acc = fc2_b[tid];
#pragma unroll 8
        for (int h = 0; h < 64; h++)
            acc += hidden[h] * fc2_w[tid * 64 + h];
        out[b * 10 + tid] = acc;
    }
}

extern "C" void kernel_launch(void* const* d_in, const int* in_sizes, int n_in,
                              void* d_out, int out_size) {
    const float* x     = (const float*)d_in[0];
    const float* w     = (const float*)d_in[1];
    const float* fc1_w = (const float*)d_in[2];
    const float* fc1_b = (const float*)d_in[3];
    const float* fc2_w = (const float*)d_in[4];
    const float* fc2_b = (const float*)d_in[5];
    float* out = (float*)d_out;

    const int B = in_sizes[0] / 784;  // 128
    qnet_kernel<<<B, THREADS>>>(x, w, fc1_w, fc1_b, fc2_w, fc2_b, out);
}

// round 12
// speedup vs baseline: 1.2346x; 1.0274x over previous
#include <cuda_runtime.h>

#define THREADS 448   // 14 warps; threads 0..391 = 196 patches x 2 sub-threads
#define NWARPS 14

typedef unsigned long long u64;

// ---- packed f32x2 primitives (sm_103a FFMA2 path) ----
__device__ __forceinline__ u64 pk2(float lo, float hi) {
    u64 r;
    asm("mov.b64 %0, {%1, %2};" : "=l"(r)
        : "r"(__float_as_uint(lo)), "r"(__float_as_uint(hi)));
    return r;
}
__device__ __forceinline__ void upk2(float& lo, float& hi, u64 v) {
    unsigned a, b;
    asm("mov.b64 {%0, %1}, %2;" : "=r"(a), "=r"(b) : "l"(v));
    lo = __uint_as_float(a); hi = __uint_as_float(b);
}
__device__ __forceinline__ u64 fma2_(u64 a, u64 b, u64 c) {
    u64 d;
    asm("fma.rn.f32x2 %0, %1, %2, %3;" : "=l"(d) : "l"(a), "l"(b), "l"(c));
    return d;
}
__device__ __forceinline__ u64 mul2_(u64 a, u64 b) {
    u64 d;
    asm("mul.rn.f32x2 %0, %1, %2;" : "=l"(d) : "l"(a), "l"(b));
    return d;
}

// Generic packed butterfly with 12 packed coeffs
// c = [pp qq nqq rr ss nss tt uu nuu vv ww nww]:
//   reA' = p*rA - q*iA + r*rB - s*iB      imA' = p*iA + q*rA + r*iB + s*rB
//   reB' = t*rA - u*iA + v*rB - w*iB      imB' = t*iA + u*rA + v*iB + w*rB
__device__ __forceinline__ void bfly12(u64& rA, u64& iA, u64& rB, u64& iB,
                                       const u64* c, bool swap_out) {
    u64 nrA = fma2_(c[5],  iB, fma2_(c[3], rB, fma2_(c[2], iA, mul2_(c[0], rA))));
    u64 niA = fma2_(c[4],  rB, fma2_(c[3], iB, fma2_(c[1], rA, mul2_(c[0], iA))));
    u64 nrB = fma2_(c[11], iB, fma2_(c[9], rB, fma2_(c[8], iA, mul2_(c[6], rA))));
    u64 niB = fma2_(c[10], rB, fma2_(c[9], iB, fma2_(c[7], rA, mul2_(c[6], iA))));
    if (swap_out) { rA = nrB; iA = niB; rB = nrA; iB = niA; }
    else          { rA = nrA; iA = niA; rB = nrB; iB = niB; }
}

__global__ __launch_bounds__(THREADS, 1)
void qnet_kernel(const float* __restrict__ x,       // [B,1,28,28]
                 const float* __restrict__ weight,  // [60]
                 const float* __restrict__ fc1_w,   // [64,784]
                 const float* __restrict__ fc1_b,   // [64]
                 const float* __restrict__ fc2_w,   // [10,64]
                 const float* __restrict__ fc2_b,   // [10]
                 float* __restrict__ out)           // [B,10]
{
    __shared__ __align__(16) float feat[784];
    __shared__ float  hidden[64];
    __shared__ float4 g[20];          // fused Ry*Rz*Ry per (layer,qubit)
    __shared__ u64 cG0[4][2][12];     // packed G0' coeffs, per layer 1..4, per sub
    __shared__ u64 cG1[4][12];        // packed G1 coeffs (sub-independent)
    __shared__ u64 cG3[4][2][6];      // packed split-q3 coeffs [P Q nQ R S nS]

    const int b   = blockIdx.x;
    const int tid = threadIdx.x;

    // ---- Stage 1: fused SU(2) gates U = Ry(p2)*Rz(p1)*Ry(p0)
    if (tid < 20) {
        const int L = tid >> 2, q = tid & 3;
        const float* p = weight + 12 * L;
        float ca, sa, cb, sb, cc, sc;
        sincosf(0.5f * p[q],     &sa, &ca);
        sincosf(0.5f * p[4 + q], &sb, &cb);
        sincosf(0.5f * p[8 + q], &sc, &cc);
        float t0 = cc * ca - sc * sa;
        float t1 = cc * ca + sc * sa;
        float t2 = cc * sa + sc * ca;
        float t3 = cc * sa - sc * ca;
        g[tid] = make_float4(cb * t0, -sb * t1, -cb * t2, sb * t3);
    }
    __syncthreads();

    // ---- Stage 2: packed coefficient banks (both sub variants)
    if (tid < 8) {
        const int li = tid >> 1, s = tid & 1;   // layer = li+1
        // G0': X30 pre-fold = column swap for sub=1
        float4 G = g[(li + 1) * 4 + 0];
        float a = G.x, bb = G.y, c = G.z, d = G.w;
        float p_, q_, r_, s_, t_, u_, v_, w_;
        if (s == 0) { p_ = a; q_ = bb; r_ = c;  s_ = d;  t_ = -c; u_ = d;   v_ = a;  w_ = -bb; }
        else        { p_ = c; q_ = d;  r_ = a;  s_ = bb; t_ = a;  u_ = -bb; v_ = -c; w_ = d; }
        u64* o = cG0[li][s];
        o[0] = pk2(p_, p_);  o[1]  = pk2(q_, q_);  o[2]  = pk2(-q_, -q_);
        o[3] = pk2(r_, r_);  o[4]  = pk2(s_, s_);  o[5]  = pk2(-s_, -s_);
        o[6] = pk2(t_, t_);  o[7]  = pk2(u_, u_);  o[8]  = pk2(-u_, -u_);
        o[9] = pk2(v_, v_);  o[10] = pk2(w_, w_);  o[11] = pk2(-w_, -w_);
        // G3': X23 post-fold = opposite-row coeffs on odd amplitudes (lane hi)
        G = g[(li + 1) * 4 + 3];
        a = G.x; bb = G.y; c = G.z; d = G.w;
        const bool rs = (li + 1) < 4;
        float Pe = a, Qe = s ? -bb : bb, Re_ = s ? -c : c, Se = d;
        float Po, Qo, Ro, So;
        if (rs) { Po = s ? c : -c; Qo = d; Ro = a; So = s ? bb : -bb; }
        else    { Po = Pe; Qo = Qe; Ro = Re_; So = Se; }
        u64* o3 = cG3[li][s];
        o3[0] = pk2(Pe, Po);   o3[1] = pk2(Qe, Qo);   o3[2] = pk2(-Qe, -Qo);
        o3[3] = pk2(Re_, Ro);  o3[4] = pk2(Se, So);   o3[5] = pk2(-Se, -So);
    } else if (tid < 12) {
        const int li = tid - 8;
        float4 G = g[(li + 1) * 4 + 1];
        float a = G.x, bb = G.y, c = G.z, d = G.w;
        u64* o = cG1[li];
        o[0] = pk2(a, a);    o[1]  = pk2(bb, bb);  o[2]  = pk2(-bb, -bb);
        o[3] = pk2(c, c);    o[4]  = pk2(d, d);    o[5]  = pk2(-d, -d);
        o[6] = pk2(-c, -c);  o[7]  = pk2(d, d);    o[8]  = pk2(-d, -d);
        o[9] = pk2(a, a);    o[10] = pk2(-bb, -bb); o[11] = pk2(bb, bb);
    }
    __syncthreads();

    // ---- Circuit: 2 threads per patch. State: 8 amps m=(b0<<2)|(b1<<1)|b2,
    // packed along b2 (LSB): zr[k] holds (re[2k], re[2k+1]), k = (b0<<1)|b1.
    {
        const int p_raw = tid >> 1;
        const bool valid = p_raw < 196;
        const int p   = valid ? p_raw : 195;
        const int sub = tid & 1;                 // qubit-3 bit

        const int pi_ = p / 14, pj = p % 14;
        const float* xb = x + b * 784 + (2 * pi_) * 28 + 2 * pj;
        const float2 xr0 = *reinterpret_cast<const float2*>(xb);
        const float2 xr1 = *reinterpret_cast<const float2*>(xb + 28);
        const float ang[4] = { xr0.x, xr0.y, xr1.x, xr1.y };

        // Layer 0 fused with Rx encoding on |0000>, ring-0 folded via
        // twisted indexing: state[m] = A(b0)*B(b0^b1)*C(b1^b2)*D(b2^sub)
        const float PI = 3.14159265358979323846f;
        float R0[4], I0[4], R1[4], I1[4];
#pragma unroll
        for (int q = 0; q < 4; q++) {
            float sx, cx;
            __sincosf(PI * ang[q], &sx, &cx);
            float4 G = g[q];
            R0[q] =  G.x * cx + G.w * sx;
            I0[q] =  G.y * cx - G.z * sx;
            R1[q] = -(G.z * cx + G.y * sx);
            I1[q] =  G.w * cx - G.x * sx;
        }

        float re[8], im[8];
        {
            float Dr[2], Di[2];
            Dr[0] = sub ? R1[3] : R0[3];  Di[0] = sub ? I1[3] : I0[3];
            Dr[1] = sub ? R0[3] : R1[3];  Di[1] = sub ? I0[3] : I1[3];
#pragma unroll
            for (int b0 = 0; b0 < 2; b0++) {
                float ar = b0 ? R1[0] : R0[0], ai = b0 ? I1[0] : I0[0];
#pragma unroll
                for (int b1 = 0; b1 < 2; b1++) {
                    int ib = b0 ^ b1;
                    float br = ib ? R1[1] : R0[1], bi = ib ? I1[1] : I0[1];
                    float abr = ar * br - ai * bi;
                    float abi = ar * bi + ai * br;
#pragma unroll
                    for (int b2 = 0; b2 < 2; b2++) {
                        int ic = b1 ^ b2;
                        float cr = ic ? R1[2] : R0[2], ci = ic ? I1[2] : I0[2];
                        float tr = abr * cr - abi * ci;
                        float ti = abr * ci + abi * cr;
                        int m = b0 * 4 + b1 * 2 + b2;
                        re[m] = tr * Dr[b2] - ti * Di[b2];
                        im[m] = tr * Di[b2] + ti * Dr[b2];
                    }
                }
            }
        }

        u64 zr[4], zi[4];
#pragma unroll
        for (int k = 0; k < 4; k++) {
            zr[k] = pk2(re[2 * k], re[2 * k + 1]);
            zi[k] = pk2(im[2 * k], im[2 * k + 1]);
        }

        // ---- Blocks 1..4 (ring folds as in R11, now packed)
#pragma unroll
        for (int layer = 1; layer < 5; layer++) {
            const int li = layer - 1;
            const bool rs = (layer < 4);

            // G0' on q0 (b0 flip): groups (k0,k2) and (k1,k3); no row swap
            {
                const u64* c = cG0[li][sub];
                bfly12(zr[0], zi[0], zr[2], zi[2], c, false);
                bfly12(zr[1], zi[1], zr[3], zi[3], c, false);
            }
            // G1' on q1 (b1 flip): groups (k0,k1) and (k2,k3);
            // X01 fold: row-swap on the b0=1 group (k2,k3)
            {
                const u64* c = cG1[li];
                bfly12(zr[0], zi[0], zr[1], zi[1], c, false);
                bfly12(zr[2], zi[2], zr[3], zi[3], c, rs);
            }
            // G2' on q2 (intra-register): scalar butterflies;
            // X12 fold: row-swap on regs with b1=1 (k&1)
            {
                float4 G = g[layer * 4 + 2];
                float a = G.x, bb = G.y, c = G.z, d = G.w;
#pragma unroll
                for (int k = 0; k < 4; k++) {
                    float r0, r1, i0, i1;
                    upk2(r0, r1, zr[k]);
                    upk2(i0, i1, zi[k]);
                    float n0r =  a * r0 - bb * i0 + c * r1 - d * i1;
                    float n0i =  a * i0 + bb * r0 + c * i1 + d * r1;
                    float n1r = -c * r0 - d * i0 + a * r1 + bb * i1;
                    float n1i = -c * i0 + d * r0 + a * i1 - bb * r1;
                    if (rs && (k & 1)) { zr[k] = pk2(n1r, n0r); zi[k] = pk2(n1i, n0i); }
                    else               { zr[k] = pk2(n0r, n1r); zi[k] = pk2(n0i, n1i); }
                }
            }
            // G3' on split q3: partner exchange + packed parity coefficients
            {
                const u64* c3 = cG3[li][sub];
#pragma unroll
                for (int k = 0; k < 4; k++) {
                    u64 pr = __shfl_xor_sync(0xffffffffu, zr[k], 1);
                    u64 pi = __shfl_xor_sync(0xffffffffu, zi[k], 1);
                    u64 nr = fma2_(c3[5], pi, fma2_(c3[3], pr, fma2_(c3[2], zi[k], mul2_(c3[0], zr[k]))));
                    u64 ni = fma2_(c3[4], pr, fma2_(c3[3], pi, fma2_(c3[1], zr[k], mul2_(c3[0], zi[k]))));
                    zr[k] = nr; zi[k] = ni;
                }
            }
        }

        // ---- <Z_q> partials (packed square), combine with partner
        float pe[4], po[4];
#pragma unroll
        for (int k = 0; k < 4; k++) {
            u64 s2 = fma2_(zr[k], zr[k], mul2_(zi[k], zi[k]));
            upk2(pe[k], po[k], s2);
        }
        // signs: e0 by k&2, e1 by k&1, e2 by lane (even +, odd -), e3 by sub
        float e0 = (pe[0] + po[0]) + (pe[1] + po[1]) - (pe[2] + po[2]) - (pe[3] + po[3]);
        float e1 = (pe[0] + po[0]) - (pe[1] + po[1]) + (pe[2] + po[2]) - (pe[3] + po[3]);
        float e2 = (pe[0] - po[0]) + (pe[1] - po[1]) + (pe[2] - po[2]) + (pe[3] - po[3]);
        float et = (pe[0] + po[0]) + (pe[1] + po[1]) + (pe[2] + po[2]) + (pe[3] + po[3]);
        float e3 = sub ? -et : et;

        e0 += __shfl_xor_sync(0xffffffffu, e0, 1);
        e1 += __shfl_xor_sync(0xffffffffu, e1, 1);
        e2 += __shfl_xor_sync(0xffffffffu, e2, 1);
        e3 += __shfl_xor_sync(0xffffffffu, e3, 1);

        if (valid && sub == 0) {
            feat[p * 4 + 0] = e0;
            feat[p * 4 + 1] = e1;
            feat[p * 4 + 2] = e2;
            feat[p * 4 + 3] = e3;
        }
    }
    __syncthreads();

    // ---- FC1 (packed): hidden[h] = relu(feat . fc1_w[h,:] + fc1_b[h])
    {
        const int warp = tid >> 5;
        const int lane = tid & 31;
        const u64* F2 = reinterpret_cast<const u64*>(feat);
        for (int h = warp; h < 64; h += NWARPS) {
            u64 acc2 = 0ull;    // packed (+0,+0)
            for (int kk = lane; kk < 196; kk += 32) {
                const ulonglong2 wv =
                    *reinterpret_cast<const ulonglong2*>(fc1_w + (h * 196 + kk) * 4);
                acc2 = fma2_(wv.x, F2[2 * kk],     acc2);
                acc2 = fma2_(wv.y, F2[2 * kk + 1], acc2);
            }
            float alo, ahi;
            upk2(alo, ahi, acc2);
            float acc = alo + ahi;
#pragma unroll
            for (int off = 16; off; off >>= 1)
                acc += __shfl_down_sync(0xffffffffu, acc, off);
            if (lane == 0)
                hidden[h] = fmaxf(acc + fc1_b[h], 0.f);
        }
    }
    __syncthreads();

    // ---- FC2
    if (tid < 10) {
        float acc = fc2_b[tid];
#pragma unroll 8
        for (int h = 0; h < 64; h++)
            acc += hidden[h] * fc2_w[tid * 64 + h];
        out[b * 10 + tid] = acc;
    }
}

extern "C" void kernel_launch(void* const* d_in, const int* in_sizes, int n_in,
                              void* d_out, int out_size) {
    const float* x     = (const float*)d_in[0];
    const float* w     = (const float*)d_in[1];
    const float* fc1_w = (const float*)d_in[2];
    const float* fc1_b = (const float*)d_in[3];
    const float* fc2_w = (const float*)d_in[4];
    const float* fc2_b = (const float*)d_in[5];
    float* out = (float*)d_out;

    const int B = in_sizes[0] / 784;  // 128
    qnet_kernel<<<B, THREADS>>>(x, w, fc1_w, fc1_b, fc2_w, fc2_b, out);
}